// round 1
// baseline (speedup 1.0000x reference)
#include <cuda_runtime.h>
#include <math.h>

#define BB 2
#define TT 12
#define CC 128
#define NHEAD 4
#define DHH 32
#define NPIX 1024          // 32*32
#define NT (BB*TT)         // 24
#define IMG (CC*NPIX)      // 131072
#define TOT (NT*IMG)       // 3145728

// ---- scratch (no allocations allowed) ----
__device__ float g_cur[TOT];
__device__ float g_v[TOT];
__device__ float g_ak[BB*NHEAD*TT*NPIX];
__device__ float g_ws[BB*CC*NPIX];
__device__ float g_att[TOT];
__device__ float g_ff1[TOT];
__device__ float g_ff2[TOT];

// ============================================================
// 3x3 SAME conv, Cin=128 -> 16 output channels per block.
// grid: (24 images, 8 co-groups), block 256.
// Each thread: 4 consecutive pixels in one row x 16 co = 64 accumulators.
// ============================================================
template<bool RELU, bool RES>
__global__ __launch_bounds__(256, 2)
void conv_ff_kernel(const float* __restrict__ in, const float* __restrict__ wgt,
                    const float* __restrict__ bias, const float* __restrict__ res,
                    float* __restrict__ out)
{
    __shared__ float splane[34*34];
    __shared__ float swgt[16*9];

    const int n   = blockIdx.x;
    const int co0 = blockIdx.y * 16;
    const int tid = threadIdx.x;
    const int pr  = tid >> 3;          // 0..31
    const int pc  = (tid & 7) * 4;     // 0..28

    float acc[16][4];
    #pragma unroll
    for (int co = 0; co < 16; ++co)
        #pragma unroll
        for (int p = 0; p < 4; ++p) acc[co][p] = 0.f;

    const float* inp = in + (size_t)n * IMG;

    for (int ci = 0; ci < 128; ++ci) {
        const float* pl = inp + ci * NPIX;
        for (int idx = tid; idx < 34*34; idx += 256) {
            int r = idx / 34 - 1, c = idx % 34 - 1;
            splane[idx] = (r >= 0 && r < 32 && c >= 0 && c < 32) ? pl[r*32 + c] : 0.f;
        }
        if (tid < 144) {
            int co = tid / 9, k = tid % 9;
            swgt[tid] = wgt[((co0 + co) * 128 + ci) * 9 + k];
        }
        __syncthreads();

        float nb[3][6];
        #pragma unroll
        for (int r = 0; r < 3; ++r)
            #pragma unroll
            for (int c = 0; c < 6; ++c)
                nb[r][c] = splane[(pr + r) * 34 + pc + c];

        #pragma unroll
        for (int co = 0; co < 16; ++co) {
            const float w0 = swgt[co*9+0], w1 = swgt[co*9+1], w2 = swgt[co*9+2];
            const float w3 = swgt[co*9+3], w4 = swgt[co*9+4], w5 = swgt[co*9+5];
            const float w6 = swgt[co*9+6], w7 = swgt[co*9+7], w8 = swgt[co*9+8];
            #pragma unroll
            for (int p = 0; p < 4; ++p) {
                float s = acc[co][p];
                s += w0*nb[0][p] + w1*nb[0][p+1] + w2*nb[0][p+2];
                s += w3*nb[1][p] + w4*nb[1][p+1] + w5*nb[1][p+2];
                s += w6*nb[2][p] + w7*nb[2][p+1] + w8*nb[2][p+2];
                acc[co][p] = s;
            }
        }
        __syncthreads();
    }

    #pragma unroll
    for (int co = 0; co < 16; ++co) {
        float bv = bias[co0 + co];
        #pragma unroll
        for (int p = 0; p < 4; ++p) {
            float v = acc[co][p] + bv;
            if (RELU) v = fmaxf(v, 0.f);
            size_t oidx = (size_t)n * IMG + (size_t)(co0 + co) * NPIX + pr * 32 + pc + p;
            if (RES) v += res[oidx];
            out[oidx] = v;
        }
    }
}

// ============================================================
// grouped kv conv: per head 32->32, 3x3 SAME.
// grid: (24 images, 8 = 4 heads x 2 co-groups of 16), block 256.
// wgt layout per layer: (4, 32, 32, 3, 3); bias (4,32).
// ============================================================
__global__ __launch_bounds__(256, 2)
void conv_kv_kernel(const float* __restrict__ in, const float* __restrict__ wgt,
                    const float* __restrict__ bias, float* __restrict__ out)
{
    __shared__ float splane[34*34];
    __shared__ float swgt[16*9];

    const int n    = blockIdx.x;
    const int head = blockIdx.y >> 1;
    const int co0  = (blockIdx.y & 1) * 16;
    const int tid  = threadIdx.x;
    const int pr   = tid >> 3;
    const int pc   = (tid & 7) * 4;

    float acc[16][4];
    #pragma unroll
    for (int co = 0; co < 16; ++co)
        #pragma unroll
        for (int p = 0; p < 4; ++p) acc[co][p] = 0.f;

    const float* inp = in + (size_t)n * IMG + (size_t)head * DHH * NPIX;

    for (int ci = 0; ci < 32; ++ci) {
        const float* pl = inp + ci * NPIX;
        for (int idx = tid; idx < 34*34; idx += 256) {
            int r = idx / 34 - 1, c = idx % 34 - 1;
            splane[idx] = (r >= 0 && r < 32 && c >= 0 && c < 32) ? pl[r*32 + c] : 0.f;
        }
        if (tid < 144) {
            int co = tid / 9, k = tid % 9;
            swgt[tid] = wgt[(((head * 32) + co0 + co) * 32 + ci) * 9 + k];
        }
        __syncthreads();

        float nb[3][6];
        #pragma unroll
        for (int r = 0; r < 3; ++r)
            #pragma unroll
            for (int c = 0; c < 6; ++c)
                nb[r][c] = splane[(pr + r) * 34 + pc + c];

        #pragma unroll
        for (int co = 0; co < 16; ++co) {
            const float w0 = swgt[co*9+0], w1 = swgt[co*9+1], w2 = swgt[co*9+2];
            const float w3 = swgt[co*9+3], w4 = swgt[co*9+4], w5 = swgt[co*9+5];
            const float w6 = swgt[co*9+6], w7 = swgt[co*9+7], w8 = swgt[co*9+8];
            #pragma unroll
            for (int p = 0; p < 4; ++p) {
                float s = acc[co][p];
                s += w0*nb[0][p] + w1*nb[0][p+1] + w2*nb[0][p+2];
                s += w3*nb[1][p] + w4*nb[1][p+1] + w5*nb[1][p+2];
                s += w6*nb[2][p] + w7*nb[2][p+1] + w8*nb[2][p+2];
                acc[co][p] = s;
            }
        }
        __syncthreads();
    }

    #pragma unroll
    for (int co = 0; co < 16; ++co) {
        float bv = bias[head * 32 + co0 + co];
        #pragma unroll
        for (int p = 0; p < 4; ++p) {
            size_t oidx = (size_t)n * IMG + (size_t)(head * 32 + co0 + co) * NPIX + pr * 32 + pc + p;
            out[oidx] = acc[co][p] + bv;
        }
    }
}

// ============================================================
// attention-key logits: ak[b,head,t,pix] = conv3x3(v + pos, attw_k[head])
// attw per layer: (4, 1, 64, 3, 3); we use in-channels [32..64) (k half).
// grid: (B*T*NHEAD) blocks, 256 threads.
// ============================================================
__global__ __launch_bounds__(256)
void ak_kernel(const float* __restrict__ v, const float* __restrict__ attw,
               float* __restrict__ ak)
{
    __shared__ float splane[34*34];
    __shared__ float sw[9];

    const int bth  = blockIdx.x;
    const int head = bth & 3;
    const int bt   = bth >> 2;       // 0..23
    const int b    = bt / TT;
    const int t    = bt % TT;
    const int tid  = threadIdx.x;
    const int pr   = tid >> 3;
    const int pc   = (tid & 7) * 4;

    float acc[4] = {0.f, 0.f, 0.f, 0.f};

    for (int ci = 0; ci < 32; ++ci) {
        // sinusoidal positional value for (t, ci), depth = 32
        const int   ii   = ci >> 1;
        const float div  = __expf(-(float)ii * (logf(10000.0f) / 16.0f));
        const float ang  = (float)t * div;
        const float posv = (ci & 1) ? cosf(ang) : sinf(ang);

        const float* pl = v + ((size_t)bt * CC + head * DHH + ci) * NPIX;
        for (int idx = tid; idx < 34*34; idx += 256) {
            int r = idx / 34 - 1, c = idx % 34 - 1;
            splane[idx] = (r >= 0 && r < 32 && c >= 0 && c < 32) ? (pl[r*32 + c] + posv) : 0.f;
        }
        if (tid < 9)
            sw[tid] = attw[((head * 64) + 32 + ci) * 9 + tid];
        __syncthreads();

        float nb[3][6];
        #pragma unroll
        for (int r = 0; r < 3; ++r)
            #pragma unroll
            for (int c = 0; c < 6; ++c)
                nb[r][c] = splane[(pr + r) * 34 + pc + c];

        const float w0 = sw[0], w1 = sw[1], w2 = sw[2];
        const float w3 = sw[3], w4 = sw[4], w5 = sw[5];
        const float w6 = sw[6], w7 = sw[7], w8 = sw[8];
        #pragma unroll
        for (int p = 0; p < 4; ++p) {
            float s = acc[p];
            s += w0*nb[0][p] + w1*nb[0][p+1] + w2*nb[0][p+2];
            s += w3*nb[1][p] + w4*nb[1][p+1] + w5*nb[1][p+2];
            s += w6*nb[2][p] + w7*nb[2][p+1] + w8*nb[2][p+2];
            acc[p] = s;
        }
        __syncthreads();
    }

    #pragma unroll
    for (int p = 0; p < 4; ++p)
        ak[(((size_t)(b * NHEAD + head) * TT) + t) * NPIX + pr * 32 + pc + p] = acc[p];
}

// ============================================================
// softmax over key-frame axis + weighted sum of v.
// (aq and att bias cancel in softmax; result independent of query frame.)
// ws[b,c,pix] = sum_t softmax_t(ak[b,head(c),t,pix]) * v[b,t,c,pix]
// 8192 threads: (b, head, pix).
// ============================================================
__global__ __launch_bounds__(256)
void softmax_ws_kernel(const float* __restrict__ ak, const float* __restrict__ v,
                       float* __restrict__ ws)
{
    const int gid  = blockIdx.x * 256 + threadIdx.x;   // 0..8191
    const int pix  = gid & 1023;
    const int head = (gid >> 10) & 3;
    const int b    = gid >> 12;

    float lg[TT];
    float m = -1e30f;
    #pragma unroll
    for (int t = 0; t < TT; ++t) {
        lg[t] = ak[(((size_t)(b * NHEAD + head) * TT) + t) * NPIX + pix];
        m = fmaxf(m, lg[t]);
    }
    float s = 0.f;
    #pragma unroll
    for (int t = 0; t < TT; ++t) { lg[t] = expf(lg[t] - m); s += lg[t]; }
    const float inv = 1.f / s;

    for (int c = 0; c < DHH; ++c) {
        float a = 0.f;
        #pragma unroll
        for (int t = 0; t < TT; ++t)
            a += lg[t] * v[((size_t)(b * TT + t) * CC + head * DHH + c) * NPIX + pix];
        ws[((size_t)b * CC + head * DHH + c) * NPIX + pix] = a * inv;
    }
}

// att_out[b,i,c,pix] = cur[b,i,c,pix] + ws[b,c,pix]   (broadcast over frames)
__global__ __launch_bounds__(256)
void add_ws_kernel(const float* __restrict__ cur, const float* __restrict__ ws,
                   float* __restrict__ out)
{
    const size_t idx = (size_t)blockIdx.x * 256 + threadIdx.x;
    if (idx >= TOT) return;
    const int pix = (int)(idx & 1023);
    const int c   = (int)((idx >> 10) & 127);
    const int bt  = (int)(idx >> 17);
    const int b   = bt / TT;
    out[idx] = cur[idx] + ws[((size_t)b * CC + c) * NPIX + pix];
}

// ============================================================
// GroupNorm: 4 groups of 32 channels, per (n, group) over 32*1024 elems.
// grid: 24*4 blocks, 256 threads.
// ============================================================
__global__ __launch_bounds__(256)
void groupnorm_kernel(const float* __restrict__ in, const float* __restrict__ gnw,
                      const float* __restrict__ gnb, float* __restrict__ out)
{
    __shared__ float rs[256], rs2[256];
    const int n  = blockIdx.x >> 2;
    const int g  = blockIdx.x & 3;
    const int tid = threadIdx.x;
    const float* p = in + (size_t)n * IMG + (size_t)g * 32 * NPIX;

    float s = 0.f, s2 = 0.f;
    for (int i = tid; i < 32 * NPIX; i += 256) {
        float x = p[i];
        s += x; s2 += x * x;
    }
    rs[tid] = s; rs2[tid] = s2;
    __syncthreads();
    for (int off = 128; off > 0; off >>= 1) {
        if (tid < off) { rs[tid] += rs[tid + off]; rs2[tid] += rs2[tid + off]; }
        __syncthreads();
    }
    const float mean = rs[0] * (1.f / 32768.f);
    const float var  = rs2[0] * (1.f / 32768.f) - mean * mean;
    const float rstd = rsqrtf(var + 1e-5f);

    float* o = out + (size_t)n * IMG + (size_t)g * 32 * NPIX;
    for (int i = tid; i < 32 * NPIX; i += 256) {
        int c = g * 32 + (i >> 10);
        o[i] = (p[i] - mean) * rstd * gnw[c] + gnb[c];
    }
}

// ============================================================
extern "C" void kernel_launch(void* const* d_in, const int* in_sizes, int n_in,
                              void* d_out, int out_size)
{
    const float* x0   = (const float*)d_in[0];
    // d_in[1]=q_w, d_in[2]=q_b, d_in[6]=att_b : provably unused (cancel in softmax)
    const float* kvw  = (const float*)d_in[3];
    const float* kvb  = (const float*)d_in[4];
    const float* attw = (const float*)d_in[5];
    const float* ff1w = (const float*)d_in[7];
    const float* ff1b = (const float*)d_in[8];
    const float* ff2w = (const float*)d_in[9];
    const float* ff2b = (const float*)d_in[10];
    const float* gnw  = (const float*)d_in[11];
    const float* gnb  = (const float*)d_in[12];

    float *cur, *v, *ak, *ws, *att, *ff1, *ff2;
    cudaGetSymbolAddress((void**)&cur, g_cur);
    cudaGetSymbolAddress((void**)&v,   g_v);
    cudaGetSymbolAddress((void**)&ak,  g_ak);
    cudaGetSymbolAddress((void**)&ws,  g_ws);
    cudaGetSymbolAddress((void**)&att, g_att);
    cudaGetSymbolAddress((void**)&ff1, g_ff1);
    cudaGetSymbolAddress((void**)&ff2, g_ff2);

    const float* lin = x0;
    for (int l = 0; l < 5; ++l) {
        conv_kv_kernel<<<dim3(NT, 8), 256>>>(lin, kvw + (size_t)l * 4 * 32 * 32 * 9,
                                             kvb + l * 128, v);
        ak_kernel<<<NT * NHEAD, 256>>>(v, attw + (size_t)l * 4 * 64 * 9, ak);
        softmax_ws_kernel<<<32, 256>>>(ak, v, ws);
        add_ws_kernel<<<TOT / 256, 256>>>(lin, ws, att);
        conv_ff_kernel<true,  false><<<dim3(NT, 8), 256>>>(att, ff1w + (size_t)l * 128 * 128 * 9,
                                                           ff1b + l * 128, nullptr, ff1);
        conv_ff_kernel<false, true ><<<dim3(NT, 8), 256>>>(ff1, ff2w + (size_t)l * 128 * 128 * 9,
                                                           ff2b + l * 128, att, ff2);
        float* lout = (l == 4) ? (float*)d_out : cur;
        groupnorm_kernel<<<NT * 4, 256>>>(ff2, gnw + l * 128, gnb + l * 128, lout);
        lin = cur;
    }
}

// round 2
// speedup vs baseline: 1.8552x; 1.8552x over previous
#include <cuda_runtime.h>
#include <math.h>

#define BB 2
#define TT 12
#define CC 128
#define NHEAD 4
#define DHH 32
#define NPIX 1024          // 32*32
#define NT (BB*TT)         // 24
#define IMG (CC*NPIX)      // 131072
#define TOT (NT*IMG)       // 3145728

typedef unsigned long long u64;

// ---- scratch (no allocations allowed) ----
__device__ float g_cur[TOT];
__device__ float g_v[TOT];
__device__ float g_ak[BB*NHEAD*TT*NPIX];
__device__ float g_ws[BB*CC*NPIX];
__device__ float g_att[TOT];
__device__ float g_ff1[TOT];
__device__ float g_ff2[TOT];

// ---- f32x2 helpers ----
__device__ __forceinline__ u64 pack2(float lo, float hi) {
    u64 r; asm("mov.b64 %0,{%1,%2};" : "=l"(r) : "f"(lo), "f"(hi)); return r;
}
__device__ __forceinline__ void unpack2(u64 v, float& lo, float& hi) {
    asm("mov.b64 {%0,%1},%2;" : "=f"(lo), "=f"(hi) : "l"(v));
}
__device__ __forceinline__ void fma2(u64& d, u64 a, u64 b) {
    asm("fma.rn.f32x2 %0, %1, %2, %3;" : "=l"(d) : "l"(a), "l"(b), "l"(d));
}

// ============================================================
// 3x3 SAME conv via packed f32x2 FMA.
// GROUPS=1: 128->128 dense (ff convs). GROUPS=4: per-head 32->32 (kv conv).
// grid: (24 images, 16 co-groups of 8), block 128.
// Thread: 2 rows x 4 cols = 8 pixels, 8 co -> 32 f32x2 accumulators.
// smem planes are halo-padded rows (34 cols x 34 rows), halo zeroed once.
// ============================================================
template<int GROUPS, bool RELU, bool RES>
__global__ __launch_bounds__(128, 3)
void conv3x3_kernel(const float* __restrict__ in, const float* __restrict__ wgt,
                    const float* __restrict__ bias, const float* __restrict__ res,
                    float* __restrict__ out)
{
    constexpr int CIN = 128 / GROUPS;
    __shared__ float splane[4 * 34 * 34];
    __shared__ u64   swgt[4 * 8 * 9];      // [ci_in_stage][co][k], duplicated (w,w)

    const int n   = blockIdx.x;
    const int co0 = blockIdx.y * 8;
    const int group    = (blockIdx.y * 8) / CIN;   // which input-channel group
    const int cin_base = group * CIN;
    const int tid = threadIdx.x;
    const int pr2 = (tid >> 3) * 2;        // output rows pr2, pr2+1 (0..30)
    const int pc  = (tid & 7) * 4;         // output cols pc..pc+3

    // zero smem (sets the halo ring; interior is overwritten each stage)
    for (int i = tid; i < 4 * 34 * 34; i += 128) splane[i] = 0.f;

    u64 acc[8][4];                          // [co][ry*2+pp]
    #pragma unroll
    for (int co = 0; co < 8; ++co)
        #pragma unroll
        for (int a = 0; a < 4; ++a) acc[co][a] = 0ull;

    const float* inp = in + (size_t)n * IMG;
    __syncthreads();

    for (int c0 = 0; c0 < CIN; c0 += 4) {
        // ---- stage 4 input planes (interior only; halo stays zero) ----
        #pragma unroll
        for (int it = 0; it < 32; ++it) {
            int i  = it * 128 + tid;        // 0..4095
            int pl = i >> 10;
            int px = i & 1023;
            int r  = px >> 5, c = px & 31;
            splane[pl * 1156 + (r + 1) * 34 + (c + 1)] =
                inp[(size_t)(cin_base + c0 + pl) * NPIX + px];
        }
        // ---- stage duplicated weights: 4ci x 8co x 9 ----
        for (int i = tid; i < 288; i += 128) {
            int ci = i / 72;
            int rm = i % 72;
            int co = rm / 9, k = rm % 9;
            float w = wgt[(((size_t)(co0 + co) * CIN) + c0 + ci) * 9 + k];
            swgt[(ci * 8 + co) * 9 + k] = pack2(w, w);
        }
        __syncthreads();

        #pragma unroll
        for (int ci = 0; ci < 4; ++ci) {
            const float* pl = &splane[ci * 1156];
            float nb[4][6];
            #pragma unroll
            for (int r = 0; r < 4; ++r)
                #pragma unroll
                for (int c = 0; c < 6; ++c)
                    nb[r][c] = pl[(pr2 + r) * 34 + pc + c];

            u64 prs[4][5];
            #pragma unroll
            for (int r = 0; r < 4; ++r)
                #pragma unroll
                for (int j = 0; j < 5; ++j)
                    prs[r][j] = pack2(nb[r][j], nb[r][j + 1]);

            #pragma unroll
            for (int co = 0; co < 8; ++co) {
                const u64* wp = &swgt[(ci * 8 + co) * 9];
                u64 w[9];
                #pragma unroll
                for (int k = 0; k < 9; ++k) w[k] = wp[k];
                #pragma unroll
                for (int ry = 0; ry < 2; ++ry)
                    #pragma unroll
                    for (int pp = 0; pp < 2; ++pp) {
                        u64 a = acc[co][ry * 2 + pp];
                        #pragma unroll
                        for (int kr = 0; kr < 3; ++kr)
                            #pragma unroll
                            for (int kc = 0; kc < 3; ++kc)
                                fma2(a, w[kr * 3 + kc], prs[ry + kr][kc + 2 * pp]);
                        acc[co][ry * 2 + pp] = a;
                    }
            }
        }
        __syncthreads();
    }

    #pragma unroll
    for (int co = 0; co < 8; ++co) {
        const float bv = bias[co0 + co];
        #pragma unroll
        for (int ry = 0; ry < 2; ++ry)
            #pragma unroll
            for (int pp = 0; pp < 2; ++pp) {
                float v0, v1;
                unpack2(acc[co][ry * 2 + pp], v0, v1);
                v0 += bv; v1 += bv;
                if (RELU) { v0 = fmaxf(v0, 0.f); v1 = fmaxf(v1, 0.f); }
                size_t oidx = (size_t)n * IMG + (size_t)(co0 + co) * NPIX
                            + (pr2 + ry) * 32 + pc + pp * 2;
                if (RES) { v0 += res[oidx]; v1 += res[oidx + 1]; }
                out[oidx]     = v0;
                out[oidx + 1] = v1;
            }
    }
}

// ============================================================
// attention-key logits: ak[b,head,t,pix] = conv3x3(v + pos, attw_k[head])
// ============================================================
__global__ __launch_bounds__(256)
void ak_kernel(const float* __restrict__ v, const float* __restrict__ attw,
               float* __restrict__ ak)
{
    __shared__ float splane[34*34];
    __shared__ float sw[9];

    const int bth  = blockIdx.x;
    const int head = bth & 3;
    const int bt   = bth >> 2;
    const int b    = bt / TT;
    const int t    = bt % TT;
    const int tid  = threadIdx.x;
    const int pr   = tid >> 3;
    const int pc   = (tid & 7) * 4;

    float acc[4] = {0.f, 0.f, 0.f, 0.f};

    for (int ci = 0; ci < 32; ++ci) {
        const int   ii   = ci >> 1;
        const float div  = __expf(-(float)ii * (logf(10000.0f) / 16.0f));
        const float ang  = (float)t * div;
        const float posv = (ci & 1) ? cosf(ang) : sinf(ang);

        const float* pl = v + ((size_t)bt * CC + head * DHH + ci) * NPIX;
        for (int idx = tid; idx < 34*34; idx += 256) {
            int r = idx / 34 - 1, c = idx % 34 - 1;
            splane[idx] = (r >= 0 && r < 32 && c >= 0 && c < 32) ? (pl[r*32 + c] + posv) : 0.f;
        }
        if (tid < 9)
            sw[tid] = attw[((head * 64) + 32 + ci) * 9 + tid];
        __syncthreads();

        float nb[3][6];
        #pragma unroll
        for (int r = 0; r < 3; ++r)
            #pragma unroll
            for (int c = 0; c < 6; ++c)
                nb[r][c] = splane[(pr + r) * 34 + pc + c];

        const float w0 = sw[0], w1 = sw[1], w2 = sw[2];
        const float w3 = sw[3], w4 = sw[4], w5 = sw[5];
        const float w6 = sw[6], w7 = sw[7], w8 = sw[8];
        #pragma unroll
        for (int p = 0; p < 4; ++p) {
            float s = acc[p];
            s += w0*nb[0][p] + w1*nb[0][p+1] + w2*nb[0][p+2];
            s += w3*nb[1][p] + w4*nb[1][p+1] + w5*nb[1][p+2];
            s += w6*nb[2][p] + w7*nb[2][p+1] + w8*nb[2][p+2];
            acc[p] = s;
        }
        __syncthreads();
    }

    #pragma unroll
    for (int p = 0; p < 4; ++p)
        ak[(((size_t)(b * NHEAD + head) * TT) + t) * NPIX + pr * 32 + pc + p] = acc[p];
}

// ============================================================
// softmax over key frames + weighted sum of v (query-independent; q path
// and attention bias cancel exactly in the softmax).
// ============================================================
__global__ __launch_bounds__(256)
void softmax_ws_kernel(const float* __restrict__ ak, const float* __restrict__ v,
                       float* __restrict__ ws)
{
    const int gid  = blockIdx.x * 256 + threadIdx.x;   // 0..8191
    const int pix  = gid & 1023;
    const int head = (gid >> 10) & 3;
    const int b    = gid >> 12;

    float lg[TT];
    float m = -1e30f;
    #pragma unroll
    for (int t = 0; t < TT; ++t) {
        lg[t] = ak[(((size_t)(b * NHEAD + head) * TT) + t) * NPIX + pix];
        m = fmaxf(m, lg[t]);
    }
    float s = 0.f;
    #pragma unroll
    for (int t = 0; t < TT; ++t) { lg[t] = expf(lg[t] - m); s += lg[t]; }
    const float inv = 1.f / s;

    for (int c = 0; c < DHH; ++c) {
        float a = 0.f;
        #pragma unroll
        for (int t = 0; t < TT; ++t)
            a += lg[t] * v[((size_t)(b * TT + t) * CC + head * DHH + c) * NPIX + pix];
        ws[((size_t)b * CC + head * DHH + c) * NPIX + pix] = a * inv;
    }
}

// att_out[b,i,c,pix] = cur[b,i,c,pix] + ws[b,c,pix]
__global__ __launch_bounds__(256)
void add_ws_kernel(const float* __restrict__ cur, const float* __restrict__ ws,
                   float* __restrict__ out)
{
    const size_t idx = (size_t)blockIdx.x * 256 + threadIdx.x;
    if (idx >= TOT) return;
    const int pix = (int)(idx & 1023);
    const int c   = (int)((idx >> 10) & 127);
    const int bt  = (int)(idx >> 17);
    const int b   = bt / TT;
    out[idx] = cur[idx] + ws[((size_t)b * CC + c) * NPIX + pix];
}

// ============================================================
// GroupNorm: 4 groups of 32 channels over 32*1024 elems.
// ============================================================
__global__ __launch_bounds__(256)
void groupnorm_kernel(const float* __restrict__ in, const float* __restrict__ gnw,
                      const float* __restrict__ gnb, float* __restrict__ out)
{
    __shared__ float rs[256], rs2[256];
    const int n  = blockIdx.x >> 2;
    const int g  = blockIdx.x & 3;
    const int tid = threadIdx.x;
    const float* p = in + (size_t)n * IMG + (size_t)g * 32 * NPIX;

    float s = 0.f, s2 = 0.f;
    for (int i = tid; i < 32 * NPIX; i += 256) {
        float x = p[i];
        s += x; s2 += x * x;
    }
    rs[tid] = s; rs2[tid] = s2;
    __syncthreads();
    for (int off = 128; off > 0; off >>= 1) {
        if (tid < off) { rs[tid] += rs[tid + off]; rs2[tid] += rs2[tid + off]; }
        __syncthreads();
    }
    const float mean = rs[0] * (1.f / 32768.f);
    const float var  = rs2[0] * (1.f / 32768.f) - mean * mean;
    const float rstd = rsqrtf(var + 1e-5f);

    float* o = out + (size_t)n * IMG + (size_t)g * 32 * NPIX;
    for (int i = tid; i < 32 * NPIX; i += 256) {
        int c = g * 32 + (i >> 10);
        o[i] = (p[i] - mean) * rstd * gnw[c] + gnb[c];
    }
}

// ============================================================
extern "C" void kernel_launch(void* const* d_in, const int* in_sizes, int n_in,
                              void* d_out, int out_size)
{
    const float* x0   = (const float*)d_in[0];
    // d_in[1]=q_w, d_in[2]=q_b, d_in[6]=att_b : cancel exactly in the softmax
    const float* kvw  = (const float*)d_in[3];
    const float* kvb  = (const float*)d_in[4];
    const float* attw = (const float*)d_in[5];
    const float* ff1w = (const float*)d_in[7];
    const float* ff1b = (const float*)d_in[8];
    const float* ff2w = (const float*)d_in[9];
    const float* ff2b = (const float*)d_in[10];
    const float* gnw  = (const float*)d_in[11];
    const float* gnb  = (const float*)d_in[12];

    float *cur, *v, *ak, *ws, *att, *ff1, *ff2;
    cudaGetSymbolAddress((void**)&cur, g_cur);
    cudaGetSymbolAddress((void**)&v,   g_v);
    cudaGetSymbolAddress((void**)&ak,  g_ak);
    cudaGetSymbolAddress((void**)&ws,  g_ws);
    cudaGetSymbolAddress((void**)&att, g_att);
    cudaGetSymbolAddress((void**)&ff1, g_ff1);
    cudaGetSymbolAddress((void**)&ff2, g_ff2);

    const float* lin = x0;
    for (int l = 0; l < 5; ++l) {
        conv3x3_kernel<4, false, false><<<dim3(NT, 16), 128>>>(
            lin, kvw + (size_t)l * 4 * 32 * 32 * 9, kvb + l * 128, nullptr, v);
        ak_kernel<<<NT * NHEAD, 256>>>(v, attw + (size_t)l * 4 * 64 * 9, ak);
        softmax_ws_kernel<<<32, 256>>>(ak, v, ws);
        add_ws_kernel<<<TOT / 256, 256>>>(lin, ws, att);
        conv3x3_kernel<1, true, false><<<dim3(NT, 16), 128>>>(
            att, ff1w + (size_t)l * 128 * 128 * 9, ff1b + l * 128, nullptr, ff1);
        conv3x3_kernel<1, false, true><<<dim3(NT, 16), 128>>>(
            ff1, ff2w + (size_t)l * 128 * 128 * 9, ff2b + l * 128, att, ff2);
        float* lout = (l == 4) ? (float*)d_out : cur;
        groupnorm_kernel<<<NT * 4, 256>>>(ff2, gnw + l * 128, gnb + l * 128, lout);
        lin = cur;
    }
}

// round 4
// speedup vs baseline: 2.0036x; 1.0800x over previous
#include <cuda_runtime.h>
#include <math.h>

#define BB 2
#define TT 12
#define CC 128
#define NHEAD 4
#define DHH 32
#define NPIX 1024          // 32*32
#define NT (BB*TT)         // 24
#define IMG (CC*NPIX)      // 131072
#define TOT (NT*IMG)       // 3145728

typedef unsigned long long u64;

// ---- scratch (no allocations allowed) ----
__device__ float g_cur[TOT];
__device__ float g_v[TOT];
__device__ float g_ak[BB*NHEAD*TT*NPIX];
__device__ float g_ws[BB*CC*NPIX];
__device__ float g_att[TOT];
__device__ float g_ff1[TOT];
__device__ float g_ff2[TOT];

// ---- f32x2 helpers ----
__device__ __forceinline__ u64 pack2(float lo, float hi) {
    u64 r; asm("mov.b64 %0,{%1,%2};" : "=l"(r) : "f"(lo), "f"(hi)); return r;
}
__device__ __forceinline__ void unpack2(u64 v, float& lo, float& hi) {
    asm("mov.b64 {%0,%1},%2;" : "=f"(lo), "=f"(hi) : "l"(v));
}
__device__ __forceinline__ void fma2(u64& d, u64 a, u64 b) {
    asm("fma.rn.f32x2 %0, %1, %2, %3;" : "=l"(d) : "l"(a), "l"(b), "l"(d));
}
__device__ __forceinline__ void cp_async4(void* smem_dst, const void* gsrc) {
    unsigned s = (unsigned)__cvta_generic_to_shared(smem_dst);
    asm volatile("cp.async.ca.shared.global [%0], [%1], 4;" :: "r"(s), "l"(gsrc));
}
__device__ __forceinline__ void cp_commit() {
    asm volatile("cp.async.commit_group;" ::: "memory");
}
__device__ __forceinline__ void cp_wait_all() {
    asm volatile("cp.async.wait_group 0;" ::: "memory");
}

__device__ __forceinline__ size_t wgidx_calc(int i, int s, int co0, int CIN) {
    int ci = i / 72; int rm = i - ci * 72; int co = rm / 9; int k = rm - co * 9;
    return (((size_t)(co0 + co) * CIN) + 4 * s + ci) * 9 + k;
}

// ============================================================
// 3x3 SAME conv via packed f32x2 FMA, double-buffered cp.async pipeline.
// GROUPS=1: 128->128 dense (ff). GROUPS=4: per-head 32->32 (kv).
// grid: (24 images, 16 co-groups of 8), block 128, 3 blocks/SM.
// Thread: 2 rows x 4 cols = 8 pixels, 8 co -> 32 f32x2 accumulators.
// ============================================================
template<int GROUPS, bool RELU, bool RES>
__global__ __launch_bounds__(128, 3)
void conv3x3_kernel(const float* __restrict__ in, const float* __restrict__ wgt,
                    const float* __restrict__ bias, const float* __restrict__ res,
                    float* __restrict__ out)
{
    constexpr int CIN = 128 / GROUPS;
    constexpr int S   = CIN / 4;           // pipeline stages (4 planes each)
    __shared__ __align__(16) float splane[2][4 * 1156];   // halo-padded 34x34
    __shared__ u64 swgt[2][4 * 8 * 9];     // [buf][ci][co][k], duplicated (w,w)

    const int n   = blockIdx.x;
    const int co0 = blockIdx.y * 8;
    const int group    = (blockIdx.y * 8) / CIN;
    const int cin_base = group * CIN;
    const int tid = threadIdx.x;
    const int pr2 = (tid >> 3) * 2;        // output rows pr2, pr2+1
    const int pc  = (tid & 7) * 4;         // output cols pc..pc+3

    const float* inp = in + (size_t)n * IMG + (size_t)cin_base * NPIX;

    // zero both buffers (halo ring; interior overwritten each stage)
    for (int i = tid; i < 4 * 1156; i += 128) { splane[0][i] = 0.f; splane[1][i] = 0.f; }

    // ---- per-thread weight slice indices (288 weights total per stage)
    const int wi0 = tid, wi1 = tid + 128, wi2 = tid + 256;   // wi2 valid if tid<32

    // plain lambdas in device code need no annotation
    auto stage_planes = [&](int s) {
        float* dst = splane[s & 1];
        const float* src = inp + (size_t)(4 * s) * NPIX;
        #pragma unroll
        for (int it = 0; it < 32; ++it) {
            int i  = it * 128 + tid;
            int pl = i >> 10, px = i & 1023;
            int r  = px >> 5, c = px & 31;
            cp_async4(&dst[pl * 1156 + (r + 1) * 34 + (c + 1)], &src[pl * NPIX + px]);
        }
        cp_commit();
    };

    u64 acc[8][4];
    #pragma unroll
    for (int co = 0; co < 8; ++co)
        #pragma unroll
        for (int a = 0; a < 4; ++a) acc[co][a] = 0ull;

    // ---- prologue ----
    float wr0, wr1, wr2;
    stage_planes(0);
    wr0 = wgt[wgidx_calc(wi0, 0, co0, CIN)];
    wr1 = wgt[wgidx_calc(wi1, 0, co0, CIN)];
    wr2 = (tid < 32) ? wgt[wgidx_calc(wi2, 0, co0, CIN)] : 0.f;
    swgt[0][wi0] = pack2(wr0, wr0);
    swgt[0][wi1] = pack2(wr1, wr1);
    if (tid < 32) swgt[0][wi2] = pack2(wr2, wr2);
    if (S > 1) {
        wr0 = wgt[wgidx_calc(wi0, 1, co0, CIN)];
        wr1 = wgt[wgidx_calc(wi1, 1, co0, CIN)];
        if (tid < 32) wr2 = wgt[wgidx_calc(wi2, 1, co0, CIN)];
    }
    cp_wait_all();
    __syncthreads();

    for (int s = 0; s < S; ++s) {
        if (s + 1 < S) {
            // stage weights for s+1 (loaded last iteration, latency hidden)
            u64* swb = swgt[(s + 1) & 1];
            swb[wi0] = pack2(wr0, wr0);
            swb[wi1] = pack2(wr1, wr1);
            if (tid < 32) swb[wi2] = pack2(wr2, wr2);
            if (s + 2 < S) {
                wr0 = wgt[wgidx_calc(wi0, s + 2, co0, CIN)];
                wr1 = wgt[wgidx_calc(wi1, s + 2, co0, CIN)];
                if (tid < 32) wr2 = wgt[wgidx_calc(wi2, s + 2, co0, CIN)];
            }
            stage_planes(s + 1);
        }

        // ---- compute stage s ----
        const float* pb = splane[s & 1];
        const u64*   wb = swgt[s & 1];
        #pragma unroll
        for (int ci = 0; ci < 4; ++ci) {
            const float* pl = &pb[ci * 1156];
            u64 prs[4][5];
            #pragma unroll
            for (int r = 0; r < 4; ++r) {
                const u64* p64 = reinterpret_cast<const u64*>(pl + (pr2 + r) * 34 + pc);
                u64 a0 = p64[0], a1 = p64[1], a2 = p64[2];
                float f0, f1, f2, f3, f4, f5;
                unpack2(a0, f0, f1); unpack2(a1, f2, f3); unpack2(a2, f4, f5);
                prs[r][0] = a0; prs[r][2] = a1; prs[r][4] = a2;
                prs[r][1] = pack2(f1, f2); prs[r][3] = pack2(f3, f4);
            }
            #pragma unroll
            for (int co = 0; co < 8; ++co) {
                const u64* wp = &wb[(ci * 8 + co) * 9];
                u64 w[9];
                #pragma unroll
                for (int k = 0; k < 9; ++k) w[k] = wp[k];
                #pragma unroll
                for (int ry = 0; ry < 2; ++ry)
                    #pragma unroll
                    for (int pp = 0; pp < 2; ++pp) {
                        u64 a = acc[co][ry * 2 + pp];
                        #pragma unroll
                        for (int kr = 0; kr < 3; ++kr)
                            #pragma unroll
                            for (int kc = 0; kc < 3; ++kc)
                                fma2(a, w[kr * 3 + kc], prs[ry + kr][kc + 2 * pp]);
                        acc[co][ry * 2 + pp] = a;
                    }
            }
        }
        if (s + 1 < S) { cp_wait_all(); __syncthreads(); }
    }

    #pragma unroll
    for (int co = 0; co < 8; ++co) {
        const float bv = bias[co0 + co];
        #pragma unroll
        for (int ry = 0; ry < 2; ++ry)
            #pragma unroll
            for (int pp = 0; pp < 2; ++pp) {
                float v0, v1;
                unpack2(acc[co][ry * 2 + pp], v0, v1);
                v0 += bv; v1 += bv;
                if (RELU) { v0 = fmaxf(v0, 0.f); v1 = fmaxf(v1, 0.f); }
                size_t oidx = (size_t)n * IMG + (size_t)(co0 + co) * NPIX
                            + (pr2 + ry) * 32 + pc + pp * 2;
                if (RES) { v0 += res[oidx]; v1 += res[oidx + 1]; }
                out[oidx]     = v0;
                out[oidx + 1] = v1;
            }
    }
}

// ============================================================
// attention-key logits: ak[b,head,t,pix] = conv3x3(v + pos, attw_k[head])
// ============================================================
__global__ __launch_bounds__(256)
void ak_kernel(const float* __restrict__ v, const float* __restrict__ attw,
               float* __restrict__ ak)
{
    __shared__ float splane[34*34];
    __shared__ float sw[9];

    const int bth  = blockIdx.x;
    const int head = bth & 3;
    const int bt   = bth >> 2;
    const int b    = bt / TT;
    const int t    = bt % TT;
    const int tid  = threadIdx.x;
    const int pr   = tid >> 3;
    const int pc   = (tid & 7) * 4;

    float acc[4] = {0.f, 0.f, 0.f, 0.f};

    for (int ci = 0; ci < 32; ++ci) {
        const int   ii   = ci >> 1;
        const float div  = __expf(-(float)ii * (logf(10000.0f) / 16.0f));
        const float ang  = (float)t * div;
        const float posv = (ci & 1) ? cosf(ang) : sinf(ang);

        const float* pl = v + ((size_t)bt * CC + head * DHH + ci) * NPIX;
        for (int idx = tid; idx < 34*34; idx += 256) {
            int r = idx / 34 - 1, c = idx % 34 - 1;
            splane[idx] = (r >= 0 && r < 32 && c >= 0 && c < 32) ? (pl[r*32 + c] + posv) : 0.f;
        }
        if (tid < 9)
            sw[tid] = attw[((head * 64) + 32 + ci) * 9 + tid];
        __syncthreads();

        float nb[3][6];
        #pragma unroll
        for (int r = 0; r < 3; ++r)
            #pragma unroll
            for (int c = 0; c < 6; ++c)
                nb[r][c] = splane[(pr + r) * 34 + pc + c];

        const float w0 = sw[0], w1 = sw[1], w2 = sw[2];
        const float w3 = sw[3], w4 = sw[4], w5 = sw[5];
        const float w6 = sw[6], w7 = sw[7], w8 = sw[8];
        #pragma unroll
        for (int p = 0; p < 4; ++p) {
            float s = acc[p];
            s += w0*nb[0][p] + w1*nb[0][p+1] + w2*nb[0][p+2];
            s += w3*nb[1][p] + w4*nb[1][p+1] + w5*nb[1][p+2];
            s += w6*nb[2][p] + w7*nb[2][p+1] + w8*nb[2][p+2];
            acc[p] = s;
        }
        __syncthreads();
    }

    #pragma unroll
    for (int p = 0; p < 4; ++p)
        ak[(((size_t)(b * NHEAD + head) * TT) + t) * NPIX + pr * 32 + pc + p] = acc[p];
}

// ============================================================
// softmax over key frames + weighted sum of v (query-independent; q path
// and attention bias cancel exactly in softmax). Channel-chunked x4.
// ============================================================
__global__ __launch_bounds__(256)
void softmax_ws_kernel(const float* __restrict__ ak, const float* __restrict__ v,
                       float* __restrict__ ws)
{
    const int chunk = blockIdx.x & 3;                     // 8 channels each
    const int gid   = (blockIdx.x >> 2) * 256 + threadIdx.x;   // 0..8191
    const int pix   = gid & 1023;
    const int head  = (gid >> 10) & 3;
    const int b     = gid >> 12;

    float lg[TT];
    float m = -1e30f;
    #pragma unroll
    for (int t = 0; t < TT; ++t) {
        lg[t] = ak[(((size_t)(b * NHEAD + head) * TT) + t) * NPIX + pix];
        m = fmaxf(m, lg[t]);
    }
    float s = 0.f;
    #pragma unroll
    for (int t = 0; t < TT; ++t) { lg[t] = expf(lg[t] - m); s += lg[t]; }
    const float inv = 1.f / s;

    const int c0 = chunk * 8;
    #pragma unroll
    for (int cc = 0; cc < 8; ++cc) {
        int c = c0 + cc;
        float a = 0.f;
        #pragma unroll
        for (int t = 0; t < TT; ++t)
            a += lg[t] * v[((size_t)(b * TT + t) * CC + head * DHH + c) * NPIX + pix];
        ws[((size_t)b * CC + head * DHH + c) * NPIX + pix] = a * inv;
    }
}

// att_out[b,i,c,pix] = cur[b,i,c,pix] + ws[b,c,pix]
__global__ __launch_bounds__(256)
void add_ws_kernel(const float* __restrict__ cur, const float* __restrict__ ws,
                   float* __restrict__ out)
{
    const size_t idx = (size_t)blockIdx.x * 256 + threadIdx.x;
    if (idx >= TOT) return;
    const int pix = (int)(idx & 1023);
    const int c   = (int)((idx >> 10) & 127);
    const int bt  = (int)(idx >> 17);
    const int b   = bt / TT;
    out[idx] = cur[idx] + ws[((size_t)b * CC + c) * NPIX + pix];
}

// ============================================================
// GroupNorm: 4 groups of 32 channels over 32*1024 elems.
// ============================================================
__global__ __launch_bounds__(256)
void groupnorm_kernel(const float* __restrict__ in, const float* __restrict__ gnw,
                      const float* __restrict__ gnb, float* __restrict__ out)
{
    __shared__ float rs[256], rs2[256];
    const int n  = blockIdx.x >> 2;
    const int g  = blockIdx.x & 3;
    const int tid = threadIdx.x;
    const float* p = in + (size_t)n * IMG + (size_t)g * 32 * NPIX;

    float s = 0.f, s2 = 0.f;
    for (int i = tid; i < 32 * NPIX; i += 256) {
        float x = p[i];
        s += x; s2 += x * x;
    }
    rs[tid] = s; rs2[tid] = s2;
    __syncthreads();
    for (int off = 128; off > 0; off >>= 1) {
        if (tid < off) { rs[tid] += rs[tid + off]; rs2[tid] += rs2[tid + off]; }
        __syncthreads();
    }
    const float mean = rs[0] * (1.f / 32768.f);
    const float var  = rs2[0] * (1.f / 32768.f) - mean * mean;
    const float rstd = rsqrtf(var + 1e-5f);

    float* o = out + (size_t)n * IMG + (size_t)g * 32 * NPIX;
    for (int i = tid; i < 32 * NPIX; i += 256) {
        int c = g * 32 + (i >> 10);
        o[i] = (p[i] - mean) * rstd * gnw[c] + gnb[c];
    }
}

// ============================================================
extern "C" void kernel_launch(void* const* d_in, const int* in_sizes, int n_in,
                              void* d_out, int out_size)
{
    const float* x0   = (const float*)d_in[0];
    // d_in[1]=q_w, d_in[2]=q_b, d_in[6]=att_b : cancel exactly in the softmax
    const float* kvw  = (const float*)d_in[3];
    const float* kvb  = (const float*)d_in[4];
    const float* attw = (const float*)d_in[5];
    const float* ff1w = (const float*)d_in[7];
    const float* ff1b = (const float*)d_in[8];
    const float* ff2w = (const float*)d_in[9];
    const float* ff2b = (const float*)d_in[10];
    const float* gnw  = (const float*)d_in[11];
    const float* gnb  = (const float*)d_in[12];

    float *cur, *v, *ak, *ws, *att, *ff1, *ff2;
    cudaGetSymbolAddress((void**)&cur, g_cur);
    cudaGetSymbolAddress((void**)&v,   g_v);
    cudaGetSymbolAddress((void**)&ak,  g_ak);
    cudaGetSymbolAddress((void**)&ws,  g_ws);
    cudaGetSymbolAddress((void**)&att, g_att);
    cudaGetSymbolAddress((void**)&ff1, g_ff1);
    cudaGetSymbolAddress((void**)&ff2, g_ff2);

    const float* lin = x0;
    for (int l = 0; l < 5; ++l) {
        conv3x3_kernel<4, false, false><<<dim3(NT, 16), 128>>>(
            lin, kvw + (size_t)l * 4 * 32 * 32 * 9, kvb + l * 128, nullptr, v);
        ak_kernel<<<NT * NHEAD, 256>>>(v, attw + (size_t)l * 4 * 64 * 9, ak);
        softmax_ws_kernel<<<128, 256>>>(ak, v, ws);
        add_ws_kernel<<<TOT / 256, 256>>>(lin, ws, att);
        conv3x3_kernel<1, true, false><<<dim3(NT, 16), 128>>>(
            att, ff1w + (size_t)l * 128 * 128 * 9, ff1b + l * 128, nullptr, ff1);
        conv3x3_kernel<1, false, true><<<dim3(NT, 16), 128>>>(
            ff1, ff2w + (size_t)l * 128 * 128 * 9, ff2b + l * 128, att, ff2);
        float* lout = (l == 4) ? (float*)d_out : cur;
        groupnorm_kernel<<<NT * 4, 256>>>(ff2, gnw + l * 128, gnb + l * 128, lout);
        lin = cur;
    }
}